// round 15
// baseline (speedup 1.0000x reference)
#include <cuda_runtime.h>
#include <cuda_fp16.h>
#include <math.h>
#include <stdint.h>

#define N_TOK 1024
#define HDIM  1024
#define IDIM  1024
#define NEXP  32
#define TOPK  4
#define NSLOT (N_TOK*TOPK)
#define T4    4

#define BM 128
#define BN 128
#define BK 64
#define NK 16
#define K4_PER_E 128     // 8 m-tiles x 16 nt per expert

#define AS_OFF(s) ((s)*16384)
#define BS_OFF(s) (32768 + (s)*16384)
#define DSMEM_BYTES (65536 + 1024)

// ---------------- device scratch ----------------
__device__ __half g_t[N_TOK*HDIM];
__device__ __half g_a[NSLOT*IDIM];
__device__ int    g_counts[NEXP];
__device__ int    g_offsets[NEXP+1];
__device__ int    g_topidx[NSLOT];
__device__ float  g_topw[NSLOT];
__device__ int    g_slot_tok[NSLOT];
__device__ float  g_slot_w[NSLOT];
__device__ int    g_done[NEXP];

// ---------------- helpers ----------------
__device__ __forceinline__ uint32_t smem_u32(const void* p) {
    uint32_t a;
    asm("{ .reg .u64 t; cvta.to.shared.u64 t, %1; cvt.u32.u64 %0, t; }" : "=r"(a) : "l"(p));
    return a;
}
__device__ __forceinline__ void cp16(uint32_t dst, const void* src) {
    asm volatile("cp.async.cg.shared.global [%0], [%1], 16;" :: "r"(dst), "l"(src));
}
#define CP_COMMIT() asm volatile("cp.async.commit_group;" ::: "memory")
#define CP_WAIT0()  asm volatile("cp.async.wait_group 0;" ::: "memory")

__device__ __forceinline__ uint32_t prmt(uint32_t a, uint32_t b, uint32_t sel) {
    uint32_t r; asm("prmt.b32 %0,%1,%2,%3;" : "=r"(r) : "r"(a), "r"(b), "r"(sel)); return r;
}
__device__ __forceinline__ uint32_t hmul2b(uint32_t a, uint32_t b) {
    uint32_t r; asm("mul.rn.f16x2 %0,%1,%2;" : "=r"(r) : "r"(a), "r"(b)); return r;
}
__device__ __forceinline__ void ldsm4(uint32_t& r0, uint32_t& r1, uint32_t& r2, uint32_t& r3,
                                      uint32_t addr) {
    asm volatile("ldmatrix.sync.aligned.m8n8.x4.shared.b16 {%0,%1,%2,%3}, [%4];"
        : "=r"(r0), "=r"(r1), "=r"(r2), "=r"(r3) : "r"(addr));
}
__device__ __forceinline__ void mma_fp16(float c[4], const uint32_t a[4], const uint32_t b[2]) {
    asm volatile("mma.sync.aligned.m16n8k16.row.col.f32.f16.f16.f32 "
        "{%0,%1,%2,%3}, {%4,%5,%6,%7}, {%8,%9}, {%0,%1,%2,%3};"
        : "+f"(c[0]), "+f"(c[1]), "+f"(c[2]), "+f"(c[3])
        : "r"(a[0]), "r"(a[1]), "r"(a[2]), "r"(a[3]), "r"(b[0]), "r"(b[1]));
}
__device__ __forceinline__ unsigned swz(unsigned byte) {
    return byte ^ ((byte >> 3) & 0x70u);
}

#define TLO 0x3E3C3800u
#define THI 0x46444240u

__device__ __forceinline__ uint4 dec8(uint4 raw, uint32_t sc2) {
    uint32_t t0 = prmt(raw.x, raw.y, 0x0040u);
    uint32_t t1 = prmt(raw.z, raw.w, 0x0040u);
    uint32_t b4 = prmt(t0, t1, 0x5410u);
    uint32_t m01 = prmt(TLO, THI, b4 & 0x7777u);
    uint32_t m23 = prmt(TLO, THI, (b4 >> 16) & 0x7777u);
    uint32_t sgnO = prmt(b4, b4, 0xBA98u);
    uint32_t be = b4 << 4;
    uint32_t sgnE = prmt(be, be, 0xBA98u);
    uint4 o;
    o.x = hmul2b(prmt(m01, 0u, 0x1404u) | (prmt(sgnE, sgnO, 0x4000u) & 0x80008000u), sc2);
    o.y = hmul2b(prmt(m01, 0u, 0x3424u) | (prmt(sgnE, sgnO, 0x5010u) & 0x80008000u), sc2);
    o.z = hmul2b(prmt(m23, 0u, 0x1404u) | (prmt(sgnE, sgnO, 0x6020u) & 0x80008000u), sc2);
    o.w = hmul2b(prmt(m23, 0u, 0x3424u) | (prmt(sgnE, sgnO, 0x7030u) & 0x80008000u), sc2);
    return o;
}

// ---------------- k0: zero counters ----------------
__global__ void k0_zero() {
    int i = threadIdx.x;
    if (i < NEXP) { g_counts[i] = 0; g_done[i] = 0; }
}

// ---------------- k1: rmsnorm + residual + gate + top4 (4 tokens/block) ----------------
__global__ __launch_bounds__(256) void k1_norm_gate(
    const float* __restrict__ x, const float* __restrict__ norm_w,
    const float* __restrict__ gate_w, const float* __restrict__ gate_b,
    float* __restrict__ out)
{
    int tb = blockIdx.x * T4;
    int tid = threadIdx.x;
    int warp = tid >> 5, lane = tid & 31;
    __shared__ float s_t[T4][HDIM];
    __shared__ float s_red[T4][8];
    __shared__ float s_log[T4][NEXP];

    float ss[T4] = {};
    #pragma unroll
    for (int t = 0; t < T4; t++) {
        const float* xr = x + (size_t)(tb + t) * HDIM;
        #pragma unroll
        for (int it = 0; it < HDIM/256; it++) {
            int i = tid + it*256;
            float v = xr[i];
            ss[t] += v*v;
            s_t[t][i] = v;
        }
    }
    #pragma unroll
    for (int t = 0; t < T4; t++) {
        float v = ss[t];
        #pragma unroll
        for (int o = 16; o; o >>= 1) v += __shfl_down_sync(0xffffffffu, v, o);
        if (lane == 0) s_red[t][warp] = v;
    }
    __syncthreads();
    if (tid < 32) {
        int t = tid >> 3, sl = tid & 7;
        float v = s_red[t][sl];
        v += __shfl_down_sync(0xffffffffu, v, 4);
        v += __shfl_down_sync(0xffffffffu, v, 2);
        v += __shfl_down_sync(0xffffffffu, v, 1);
        if (sl == 0) s_red[t][0] = v;
    }
    __syncthreads();
    float scale[T4];
    #pragma unroll
    for (int t = 0; t < T4; t++)
        scale[t] = rsqrtf(s_red[t][0] * (1.f / HDIM) + 1e-5f);

    #pragma unroll
    for (int it = 0; it < HDIM/256; it++) {
        int i = tid + it*256;
        float nw = norm_w[i];
        #pragma unroll
        for (int t = 0; t < T4; t++) {
            float xv = s_t[t][i];
            out[(size_t)(tb + t)*HDIM + i] = xv;
            float tv = xv * scale[t] * nw;
            s_t[t][i] = tv;
            g_t[(size_t)(tb + t)*HDIM + i] = __float2half_rn(tv);
        }
    }
    __syncthreads();

    for (int e = warp; e < NEXP; e += 8) {
        const float* gw = gate_w + (size_t)e * HDIM;
        float a0 = 0.f, a1 = 0.f, a2 = 0.f, a3 = 0.f;
        for (int i = lane; i < HDIM; i += 32) {
            float g = gw[i];
            a0 += s_t[0][i]*g; a1 += s_t[1][i]*g;
            a2 += s_t[2][i]*g; a3 += s_t[3][i]*g;
        }
        #pragma unroll
        for (int o = 16; o; o >>= 1) {
            a0 += __shfl_down_sync(0xffffffffu, a0, o);
            a1 += __shfl_down_sync(0xffffffffu, a1, o);
            a2 += __shfl_down_sync(0xffffffffu, a2, o);
            a3 += __shfl_down_sync(0xffffffffu, a3, o);
        }
        if (lane == 0) {
            float gb = gate_b[e];
            s_log[0][e] = a0 + gb; s_log[1][e] = a1 + gb;
            s_log[2][e] = a2 + gb; s_log[3][e] = a3 + gb;
        }
    }
    __syncthreads();

    if (tid < T4) {
        int tok = tb + tid;
        int idx[TOPK]; float val[TOPK];
        unsigned mask = 0;
        #pragma unroll
        for (int k = 0; k < TOPK; k++) {
            float best = -1e30f; int bi = 0;
            for (int e = 0; e < NEXP; e++)
                if (!((mask >> e) & 1u) && s_log[tid][e] > best) { best = s_log[tid][e]; bi = e; }
            mask |= 1u << bi; idx[k] = bi; val[k] = best;
        }
        float mx = val[0];
        float se = 0.f;
        #pragma unroll
        for (int k = 0; k < TOPK; k++) { val[k] = expf(val[k] - mx); se += val[k]; }
        float inv = 1.f / se;
        #pragma unroll
        for (int k = 0; k < TOPK; k++) {
            g_topidx[tok*TOPK + k] = idx[k];
            g_topw[tok*TOPK + k]  = val[k] * inv;
            atomicAdd(&g_counts[idx[k]], 1);
        }
    }
}

// ---------------- k2: scan + scatter ----------------
__global__ __launch_bounds__(1024) void k2_route() {
    __shared__ int s_cur[NEXP];
    __shared__ int s_off[NEXP];
    int tid = threadIdx.x;
    if (tid == 0) {
        int s = 0;
        for (int e = 0; e < NEXP; e++) {
            s_off[e] = s; g_offsets[e] = s; s += g_counts[e];
        }
        g_offsets[NEXP] = s;
    }
    if (tid < NEXP) s_cur[tid] = 0;
    __syncthreads();
    #pragma unroll
    for (int p = 0; p < NSLOT/1024; p++) {
        int i = tid + p*1024;
        int e = g_topidx[i];
        int pos = s_off[e] + atomicAdd(&s_cur[e], 1);
        g_slot_tok[pos] = i >> 2;
        g_slot_w[pos]   = g_topw[i];
    }
}

// ================= k4 body: mlp1 tile =================
__device__ void k4_body(
    int e, int mt, int nt, char* sb, uint32_t sb32,
    const int* __restrict__ blocks, const int* __restrict__ scales,
    const float* __restrict__ bias)
{
    int cnt = g_counts[e];
    int m0 = mt * BM;
    if (m0 >= cnt) {
        if (threadIdx.x == 0) atomicAdd(&g_done[e], 1);
        return;
    }
    bool do2 = (m0 + 64 < cnt);
    int off = g_offsets[e];

    __shared__ int s_tok[BM];

    const int ROWS = 2*IDIM, GRPS = HDIM/32;
    int tid = threadIdx.x;
    int lane = tid & 31, wid = tid >> 5;
    int wm = wid >> 2, wn = wid & 3;

    for (int i = tid; i < BM; i += 256) {
        int m = m0 + i;
        s_tok[i] = (m < cnt) ? g_slot_tok[off + m] : 0;
    }
    __syncthreads();

    int ci[4], cn[4], cj[4];
    #pragma unroll
    for (int p = 0; p < 4; p++) {
        ci[p] = (tid >> 5)*128 + p*32 + lane;
        cn[p] = ci[p] >> 3; cj[p] = ci[p] & 7;
    }
    const int* wbase = blocks + ((size_t)e*ROWS + nt*BN)*(size_t)GRPS*16;
    const int* sbase = scales + ((size_t)e*ROWS + nt*BN)*(size_t)GRPS;

    uint4    rw[4];
    uint32_t scl[4];

    auto issueLdg = [&](int kt) {
        #pragma unroll
        for (int p = 0; p < 4; p++) {
            rw[p] = *(const uint4*)(wbase + (size_t)cn[p]*GRPS*16
                                    + (kt*2 + (cj[p]>>2))*16 + (cj[p]&3)*4);
            scl[p] = (uint32_t)__ldg(sbase + cn[p]*GRPS + kt*2 + (cj[p]>>2));
        }
    };
    auto issueCp = [&](int kt) {
        int s = kt & 1;
        int c = tid & 7, mr = tid >> 3;
        cp16(sb32 + AS_OFF(s) + swz(mr*128 + c*16),
             g_t + (size_t)s_tok[mr]*HDIM + kt*BK + c*8);
        cp16(sb32 + AS_OFF(s) + swz((mr+32)*128 + c*16),
             g_t + (size_t)s_tok[mr+32]*HDIM + kt*BK + c*8);
        if (do2) {
            cp16(sb32 + AS_OFF(s) + swz((mr+64)*128 + c*16),
                 g_t + (size_t)s_tok[mr+64]*HDIM + kt*BK + c*8);
            cp16(sb32 + AS_OFF(s) + swz((mr+96)*128 + c*16),
                 g_t + (size_t)s_tok[mr+96]*HDIM + kt*BK + c*8);
        }
        CP_COMMIT();
    };
    auto decode = [&](int kt) {
        int s = kt & 1;
        #pragma unroll
        for (int p = 0; p < 4; p++) {
            uint32_t sc2 = ((scl[p] - 112u) << 10) * 0x00010001u;
            uint4 o = dec8(rw[p], sc2);
            *(uint4*)(sb + BS_OFF(s) + swz(cn[p]*128 + cj[p]*16)) = o;
        }
    };

    float acc[2][2][4][4] = {};

    issueCp(0);
    issueLdg(0);
    CP_WAIT0();
    decode(0);

    #pragma unroll 1
    for (int kt = 0; kt < NK; kt++) {
        int s = kt & 1;
        if (kt + 1 < NK) issueLdg(kt + 1);
        __syncthreads();
        if (kt + 1 < NK) issueCp(kt + 1);
        uint32_t Ab = sb32 + AS_OFF(s), Bb = sb32 + BS_OFF(s);
        #pragma unroll
        for (int kk = 0; kk < 4; kk++) {
            uint32_t b[4][2];
            {
                int r = lane & 7, kb = (lane >> 3) & 1, nb = lane >> 4;
                #pragma unroll
                for (int g2 = 0; g2 < 2; g2++) {
                    uint32_t ad = Bb + swz((wn*32 + g2*16 + nb*8 + r)*128 + kk*32 + kb*16);
                    ldsm4(b[2*g2][0], b[2*g2][1], b[2*g2+1][0], b[2*g2+1][1], ad);
                }
            }
            int r = lane & 7, sel = (lane >> 3) & 1, ks = lane >> 4;
            uint32_t a[2][4];
            #pragma unroll
            for (int h = 0; h < 2; h++) {
                uint32_t ad = Ab + swz((wm*32 + h*16 + sel*8 + r)*128 + kk*32 + ks*16);
                ldsm4(a[h][0], a[h][1], a[h][2], a[h][3], ad);
            }
            #pragma unroll
            for (int h = 0; h < 2; h++)
                #pragma unroll
                for (int g = 0; g < 4; g++)
                    mma_fp16(acc[0][h][g], a[h], b[g]);
            if (do2) {
                #pragma unroll
                for (int h = 0; h < 2; h++) {
                    uint32_t ad = Ab + swz((64 + wm*32 + h*16 + sel*8 + r)*128 + kk*32 + ks*16);
                    ldsm4(a[h][0], a[h][1], a[h][2], a[h][3], ad);
                }
                #pragma unroll
                for (int h = 0; h < 2; h++)
                    #pragma unroll
                    for (int g = 0; g < 4; g++)
                        mma_fp16(acc[1][h][g], a[h], b[g]);
            }
        }
        if (kt + 1 < NK) { decode(kt + 1); CP_WAIT0(); }
    }

    #pragma unroll
    for (int t = 0; t < 2; t++) {
        #pragma unroll
        for (int h = 0; h < 2; h++) {
            #pragma unroll
            for (int half = 0; half < 2; half++) {
                int m = m0 + t*64 + wm*32 + h*16 + (lane >> 2) + half*8;
                if (m >= cnt) continue;
                int slot = off + m;
                #pragma unroll
                for (int g = 0; g < 4; g++) {
                    int gcol = nt*BN + wn*32 + g*8 + 2*(lane & 3);
                    float hg = acc[t][h][g][half*2+0] + bias[(size_t)e*ROWS + gcol];
                    float hl = acc[t][h][g][half*2+1] + bias[(size_t)e*ROWS + gcol + 1];
                    hg = fminf(hg, 7.f);
                    hl = fminf(fmaxf(hl, -7.f), 7.f);
                    float aa = hg * (1.f / (1.f + expf(-1.702f * hg))) * (hl + 1.f);
                    g_a[(size_t)slot*IDIM + (gcol >> 1)] = __float2half_rn(aa);
                }
            }
        }
    }
    __threadfence();
    __syncthreads();
    if (threadIdx.x == 0) atomicAdd(&g_done[e], 1);
}

// ================= k5 body: mlp2 tile (waits on expert's k4 tiles) =================
__device__ void k5_body(
    int e, int mt, int nt, char* sb, uint32_t sb32,
    const int* __restrict__ blocks, const int* __restrict__ scales,
    const float* __restrict__ bias, float* __restrict__ out)
{
    int cnt = g_counts[e];
    int m0 = mt * BM;
    if (m0 >= cnt) return;
    bool do2 = (m0 + 64 < cnt);
    int off = g_offsets[e];

    __shared__ int   s_tok[BM];
    __shared__ float s_w[BM];

    const int ROWS = HDIM, GRPS = IDIM/32;
    int tid = threadIdx.x;
    int lane = tid & 31, wid = tid >> 5;
    int wm = wid >> 2, wn = wid & 3;

    for (int i = tid; i < BM; i += 256) {
        int m = m0 + i;
        s_tok[i] = (m < cnt) ? g_slot_tok[off + m] : 0;
        s_w[i]   = (m < cnt) ? g_slot_w[off + m] : 0.f;
    }

    // wait for this expert's mlp1 tiles to complete
    if (tid == 0) {
        while (*(volatile int*)&g_done[e] < K4_PER_E) __nanosleep(128);
    }
    __syncthreads();

    int ci[4], cn[4], cj[4];
    #pragma unroll
    for (int p = 0; p < 4; p++) {
        ci[p] = (tid >> 5)*128 + p*32 + lane;
        cn[p] = ci[p] >> 3; cj[p] = ci[p] & 7;
    }
    const int* wbase = blocks + ((size_t)e*ROWS + nt*BN)*(size_t)GRPS*16;
    const int* sbase = scales + ((size_t)e*ROWS + nt*BN)*(size_t)GRPS;

    uint4    rw[4];
    uint32_t scl[4];

    auto issueLdg = [&](int kt) {
        #pragma unroll
        for (int p = 0; p < 4; p++) {
            rw[p] = *(const uint4*)(wbase + (size_t)cn[p]*GRPS*16
                                    + (kt*2 + (cj[p]>>2))*16 + (cj[p]&3)*4);
            scl[p] = (uint32_t)__ldg(sbase + cn[p]*GRPS + kt*2 + (cj[p]>>2));
        }
    };
    auto issueCp = [&](int kt) {
        int s = kt & 1;
        int c = tid & 7, mr = tid >> 3;
        int r0 = off + m0 + mr;       if (r0 > NSLOT-1) r0 = NSLOT-1;
        int r1 = off + m0 + mr + 32;  if (r1 > NSLOT-1) r1 = NSLOT-1;
        cp16(sb32 + AS_OFF(s) + swz(mr*128 + c*16), g_a + (size_t)r0*IDIM + kt*BK + c*8);
        cp16(sb32 + AS_OFF(s) + swz((mr+32)*128 + c*16), g_a + (size_t)r1*IDIM + kt*BK + c*8);
        if (do2) {
            int r2 = off + m0 + mr + 64;  if (r2 > NSLOT-1) r2 = NSLOT-1;
            int r3 = off + m0 + mr + 96;  if (r3 > NSLOT-1) r3 = NSLOT-1;
            cp16(sb32 + AS_OFF(s) + swz((mr+64)*128 + c*16), g_a + (size_t)r2*IDIM + kt*BK + c*8);
            cp16(sb32 + AS_OFF(s) + swz((mr+96)*128 + c*16), g_a + (size_t)r3*IDIM + kt*BK + c*8);
        }
        CP_COMMIT();
    };
    auto decode = [&](int kt) {
        int s = kt & 1;
        #pragma unroll
        for (int p = 0; p < 4; p++) {
            uint32_t sc2 = ((scl[p] - 112u) << 10) * 0x00010001u;
            uint4 o = dec8(rw[p], sc2);
            *(uint4*)(sb + BS_OFF(s) + swz(cn[p]*128 + cj[p]*16)) = o;
        }
    };

    float acc[2][2][4][4] = {};

    issueCp(0);
    issueLdg(0);
    CP_WAIT0();
    decode(0);

    #pragma unroll 1
    for (int kt = 0; kt < NK; kt++) {
        int s = kt & 1;
        if (kt + 1 < NK) issueLdg(kt + 1);
        __syncthreads();
        if (kt + 1 < NK) issueCp(kt + 1);
        uint32_t Ab = sb32 + AS_OFF(s), Bb = sb32 + BS_OFF(s);
        #pragma unroll
        for (int kk = 0; kk < 4; kk++) {
            uint32_t b[4][2];
            {
                int r = lane & 7, kb = (lane >> 3) & 1, nb = lane >> 4;
                #pragma unroll
                for (int g2 = 0; g2 < 2; g2++) {
                    uint32_t ad = Bb + swz((wn*32 + g2*16 + nb*8 + r)*128 + kk*32 + kb*16);
                    ldsm4(b[2*g2][0], b[2*g2][1], b[2*g2+1][0], b[2*g2+1][1], ad);
                }
            }
            int r = lane & 7, sel = (lane >> 3) & 1, ks = lane >> 4;
            uint32_t a[2][4];
            #pragma unroll
            for (int h = 0; h < 2; h++) {
                uint32_t ad = Ab + swz((wm*32 + h*16 + sel*8 + r)*128 + kk*32 + ks*16);
                ldsm4(a[h][0], a[h][1], a[h][2], a[h][3], ad);
            }
            #pragma unroll
            for (int h = 0; h < 2; h++)
                #pragma unroll
                for (int g = 0; g < 4; g++)
                    mma_fp16(acc[0][h][g], a[h], b[g]);
            if (do2) {
                #pragma unroll
                for (int h = 0; h < 2; h++) {
                    uint32_t ad = Ab + swz((64 + wm*32 + h*16 + sel*8 + r)*128 + kk*32 + ks*16);
                    ldsm4(a[h][0], a[h][1], a[h][2], a[h][3], ad);
                }
                #pragma unroll
                for (int h = 0; h < 2; h++)
                    #pragma unroll
                    for (int g = 0; g < 4; g++)
                        mma_fp16(acc[1][h][g], a[h], b[g]);
            }
        }
        if (kt + 1 < NK) { decode(kt + 1); CP_WAIT0(); }
    }

    #pragma unroll
    for (int t = 0; t < 2; t++) {
        #pragma unroll
        for (int h = 0; h < 2; h++) {
            #pragma unroll
            for (int half = 0; half < 2; half++) {
                int mi = t*64 + wm*32 + h*16 + (lane >> 2) + half*8;
                if (m0 + mi >= cnt) continue;
                int tok = s_tok[mi];
                float rwt = s_w[mi];
                #pragma unroll
                for (int g = 0; g < 4; g++) {
                    int gcol = nt*BN + wn*32 + g*8 + 2*(lane & 3);
                    float y0 = acc[t][h][g][half*2+0] + bias[(size_t)e*HDIM + gcol];
                    float y1 = acc[t][h][g][half*2+1] + bias[(size_t)e*HDIM + gcol + 1];
                    atomicAdd(&out[(size_t)tok*HDIM + gcol],     rwt * y0);
                    atomicAdd(&out[(size_t)tok*HDIM + gcol + 1], rwt * y1);
                }
            }
        }
    }
}

// ================= fused k45: interleaved mlp1/mlp2 tiles =================
// order: [k4 e0 (128)] then per grp 0..30: [k5 e=grp (64)][k4 e=grp+1 (128)],
// then [k5 e31 (64)]. Every block waits only on lower-indexed blocks.
__global__ __launch_bounds__(256, 2) void k45(
    const int* __restrict__ b1, const int* __restrict__ s1, const float* __restrict__ bias1,
    const int* __restrict__ b2, const int* __restrict__ s2, const float* __restrict__ bias2,
    float* __restrict__ out)
{
    extern __shared__ char dsm[];
    char* sb = (char*)(((uintptr_t)dsm + 1023) & ~(uintptr_t)1023);
    uint32_t sb32 = smem_u32(sb);

    int idx = blockIdx.x;
    int role, e, sub;
    if (idx < 128) { role = 0; e = 0; sub = idx; }
    else if (idx < 6080) {
        int j = idx - 128;
        int grp = j / 192, r = j % 192;
        if (r < 64) { role = 1; e = grp;     sub = r; }
        else        { role = 0; e = grp + 1; sub = r - 64; }
    } else { role = 1; e = 31; sub = idx - 6080; }

    if (role == 0) k4_body(e, sub & 7, sub >> 3, sb, sb32, b1, s1, bias1);
    else           k5_body(e, sub & 7, sub >> 3, sb, sb32, b2, s2, bias2, out);
}

// ---------------- launch ----------------
extern "C" void kernel_launch(void* const* d_in, const int* in_sizes, int n_in,
                              void* d_out, int out_size)
{
    const float* x          = (const float*)d_in[0];
    const float* norm_w     = (const float*)d_in[1];
    const float* gate_w     = (const float*)d_in[2];
    const float* gate_b     = (const float*)d_in[3];
    const float* mlp1_bias  = (const float*)d_in[4];
    const float* mlp2_bias  = (const float*)d_in[5];
    const int*   mlp1_blocks= (const int*)d_in[6];
    const int*   mlp1_scales= (const int*)d_in[7];
    const int*   mlp2_blocks= (const int*)d_in[8];
    const int*   mlp2_scales= (const int*)d_in[9];
    float* out = (float*)d_out;

    cudaFuncSetAttribute(k45, cudaFuncAttributeMaxDynamicSharedMemorySize, DSMEM_BYTES);

    k0_zero<<<1, 32>>>();
    k1_norm_gate<<<N_TOK/T4, 256>>>(x, norm_w, gate_w, gate_b, out);
    k2_route<<<1, 1024>>>();
    k45<<<6144, 256, DSMEM_BYTES>>>(mlp1_blocks, mlp1_scales, mlp1_bias,
                                    mlp2_blocks, mlp2_scales, mlp2_bias, out);
}

// round 16
// speedup vs baseline: 1.2659x; 1.2659x over previous
#include <cuda_runtime.h>
#include <cuda_fp16.h>
#include <math.h>
#include <stdint.h>

#define N_TOK 1024
#define HDIM  1024
#define IDIM  1024
#define NEXP  32
#define TOPK  4
#define NSLOT (N_TOK*TOPK)
#define T4    4

#define BM 128           // 2 x 64-row subtiles sharing decoded B
#define BN 128
#define BK 64
#define NK 16            // 1024 / 64
#define KSPLIT 2
#define NKH (NK/KSPLIT)  // 8 k-tiles per split half

// dynamic smem (bytes from 1024-aligned base)
#define AS_OFF(s) ((s)*16384)              // 2 x 16KB A tiles (fp16 128x64)
#define BS_OFF(s) (32768 + (s)*16384)      // 2 x 16KB decoded B tiles
#define DSMEM_BYTES (65536 + 1024)

// ---------------- device scratch ----------------
__device__ __half g_t[N_TOK*HDIM];
__device__ __half g_a[NSLOT*IDIM];
__device__ int    g_counts[NEXP];
__device__ int    g_offsets[NEXP+1];
__device__ int    g_topidx[NSLOT];
__device__ float  g_topw[NSLOT];
__device__ int    g_slot_tok[NSLOT];
__device__ float  g_slot_w[NSLOT];

// ---------------- helpers ----------------
__device__ __forceinline__ uint32_t smem_u32(const void* p) {
    uint32_t a;
    asm("{ .reg .u64 t; cvta.to.shared.u64 t, %1; cvt.u32.u64 %0, t; }" : "=r"(a) : "l"(p));
    return a;
}
__device__ __forceinline__ void cp16(uint32_t dst, const void* src) {
    asm volatile("cp.async.cg.shared.global [%0], [%1], 16;" :: "r"(dst), "l"(src));
}
#define CP_COMMIT() asm volatile("cp.async.commit_group;" ::: "memory")
#define CP_WAIT0()  asm volatile("cp.async.wait_group 0;" ::: "memory")

__device__ __forceinline__ uint32_t prmt(uint32_t a, uint32_t b, uint32_t sel) {
    uint32_t r; asm("prmt.b32 %0,%1,%2,%3;" : "=r"(r) : "r"(a), "r"(b), "r"(sel)); return r;
}
__device__ __forceinline__ uint32_t hmul2b(uint32_t a, uint32_t b) {
    uint32_t r; asm("mul.rn.f16x2 %0,%1,%2;" : "=r"(r) : "r"(a), "r"(b)); return r;
}
__device__ __forceinline__ void ldsm4(uint32_t& r0, uint32_t& r1, uint32_t& r2, uint32_t& r3,
                                      uint32_t addr) {
    asm volatile("ldmatrix.sync.aligned.m8n8.x4.shared.b16 {%0,%1,%2,%3}, [%4];"
        : "=r"(r0), "=r"(r1), "=r"(r2), "=r"(r3) : "r"(addr));
}
__device__ __forceinline__ void mma_fp16(float c[4], const uint32_t a[4], const uint32_t b[2]) {
    asm volatile("mma.sync.aligned.m16n8k16.row.col.f32.f16.f16.f32 "
        "{%0,%1,%2,%3}, {%4,%5,%6,%7}, {%8,%9}, {%0,%1,%2,%3};"
        : "+f"(c[0]), "+f"(c[1]), "+f"(c[2]), "+f"(c[3])
        : "r"(a[0]), "r"(a[1]), "r"(a[2]), "r"(a[3]), "r"(b[0]), "r"(b[1]));
}
__device__ __forceinline__ unsigned swz(unsigned byte) {
    return byte ^ ((byte >> 3) & 0x70u);
}

// PRMT fp4 magnitude tables: high bytes of fp16 {0,.5,1,1.5,2,3,4,6}
#define TLO 0x3E3C3800u
#define THI 0x46444240u

// decode 4 raw ints (8 fp4 values) -> uint4 of 4 fp16x2, scaled (exact)
__device__ __forceinline__ uint4 dec8(uint4 raw, uint32_t sc2) {
    uint32_t t0 = prmt(raw.x, raw.y, 0x0040u);
    uint32_t t1 = prmt(raw.z, raw.w, 0x0040u);
    uint32_t b4 = prmt(t0, t1, 0x5410u);        // 8 nibbles packed
    uint32_t m01 = prmt(TLO, THI, b4 & 0x7777u);
    uint32_t m23 = prmt(TLO, THI, (b4 >> 16) & 0x7777u);
    uint32_t sgnO = prmt(b4, b4, 0xBA98u);      // odd-nibble sign byte-masks
    uint32_t be = b4 << 4;
    uint32_t sgnE = prmt(be, be, 0xBA98u);      // even-nibble sign byte-masks
    uint4 o;
    o.x = hmul2b(prmt(m01, 0u, 0x1404u) | (prmt(sgnE, sgnO, 0x4000u) & 0x80008000u), sc2);
    o.y = hmul2b(prmt(m01, 0u, 0x3424u) | (prmt(sgnE, sgnO, 0x5010u) & 0x80008000u), sc2);
    o.z = hmul2b(prmt(m23, 0u, 0x1404u) | (prmt(sgnE, sgnO, 0x6020u) & 0x80008000u), sc2);
    o.w = hmul2b(prmt(m23, 0u, 0x3424u) | (prmt(sgnE, sgnO, 0x7030u) & 0x80008000u), sc2);
    return o;
}

// ---------------- k0: zero counters ----------------
__global__ void k0_zero() {
    int i = threadIdx.x;
    if (i < NEXP) g_counts[i] = 0;
}

// ---------------- k1: rmsnorm + residual + gate + top4 (4 tokens/block) ----------------
__global__ __launch_bounds__(256) void k1_norm_gate(
    const float* __restrict__ x, const float* __restrict__ norm_w,
    const float* __restrict__ gate_w, const float* __restrict__ gate_b,
    float* __restrict__ out)
{
    int tb = blockIdx.x * T4;
    int tid = threadIdx.x;
    int warp = tid >> 5, lane = tid & 31;
    __shared__ float s_t[T4][HDIM];
    __shared__ float s_red[T4][8];
    __shared__ float s_log[T4][NEXP];

    float ss[T4] = {};
    #pragma unroll
    for (int t = 0; t < T4; t++) {
        const float* xr = x + (size_t)(tb + t) * HDIM;
        #pragma unroll
        for (int it = 0; it < HDIM/256; it++) {
            int i = tid + it*256;
            float v = xr[i];
            ss[t] += v*v;
            s_t[t][i] = v;
        }
    }
    #pragma unroll
    for (int t = 0; t < T4; t++) {
        float v = ss[t];
        #pragma unroll
        for (int o = 16; o; o >>= 1) v += __shfl_down_sync(0xffffffffu, v, o);
        if (lane == 0) s_red[t][warp] = v;
    }
    __syncthreads();
    if (tid < 32) {
        int t = tid >> 3, sl = tid & 7;
        float v = s_red[t][sl];
        v += __shfl_down_sync(0xffffffffu, v, 4);
        v += __shfl_down_sync(0xffffffffu, v, 2);
        v += __shfl_down_sync(0xffffffffu, v, 1);
        if (sl == 0) s_red[t][0] = v;
    }
    __syncthreads();
    float scale[T4];
    #pragma unroll
    for (int t = 0; t < T4; t++)
        scale[t] = rsqrtf(s_red[t][0] * (1.f / HDIM) + 1e-5f);

    #pragma unroll
    for (int it = 0; it < HDIM/256; it++) {
        int i = tid + it*256;
        float nw = norm_w[i];
        #pragma unroll
        for (int t = 0; t < T4; t++) {
            float xv = s_t[t][i];
            out[(size_t)(tb + t)*HDIM + i] = xv;            // residual init
            float tv = xv * scale[t] * nw;
            s_t[t][i] = tv;
            g_t[(size_t)(tb + t)*HDIM + i] = __float2half_rn(tv);
        }
    }
    __syncthreads();

    for (int e = warp; e < NEXP; e += 8) {
        const float* gw = gate_w + (size_t)e * HDIM;
        float a0 = 0.f, a1 = 0.f, a2 = 0.f, a3 = 0.f;
        for (int i = lane; i < HDIM; i += 32) {
            float g = gw[i];
            a0 += s_t[0][i]*g; a1 += s_t[1][i]*g;
            a2 += s_t[2][i]*g; a3 += s_t[3][i]*g;
        }
        #pragma unroll
        for (int o = 16; o; o >>= 1) {
            a0 += __shfl_down_sync(0xffffffffu, a0, o);
            a1 += __shfl_down_sync(0xffffffffu, a1, o);
            a2 += __shfl_down_sync(0xffffffffu, a2, o);
            a3 += __shfl_down_sync(0xffffffffu, a3, o);
        }
        if (lane == 0) {
            float gb = gate_b[e];
            s_log[0][e] = a0 + gb; s_log[1][e] = a1 + gb;
            s_log[2][e] = a2 + gb; s_log[3][e] = a3 + gb;
        }
    }
    __syncthreads();

    if (tid < T4) {
        int tok = tb + tid;
        int idx[TOPK]; float val[TOPK];
        unsigned mask = 0;
        #pragma unroll
        for (int k = 0; k < TOPK; k++) {
            float best = -1e30f; int bi = 0;
            for (int e = 0; e < NEXP; e++)
                if (!((mask >> e) & 1u) && s_log[tid][e] > best) { best = s_log[tid][e]; bi = e; }
            mask |= 1u << bi; idx[k] = bi; val[k] = best;
        }
        float mx = val[0];
        float se = 0.f;
        #pragma unroll
        for (int k = 0; k < TOPK; k++) { val[k] = expf(val[k] - mx); se += val[k]; }
        float inv = 1.f / se;
        #pragma unroll
        for (int k = 0; k < TOPK; k++) {
            g_topidx[tok*TOPK + k] = idx[k];
            g_topw[tok*TOPK + k]  = val[k] * inv;
            atomicAdd(&g_counts[idx[k]], 1);
        }
    }
}

// ---------------- k2: scan + scatter (single block) ----------------
__global__ __launch_bounds__(1024) void k2_route() {
    __shared__ int s_cur[NEXP];
    __shared__ int s_off[NEXP];
    int tid = threadIdx.x;
    if (tid == 0) {
        int s = 0;
        for (int e = 0; e < NEXP; e++) {
            s_off[e] = s; g_offsets[e] = s; s += g_counts[e];
        }
        g_offsets[NEXP] = s;
    }
    if (tid < NEXP) s_cur[tid] = 0;
    __syncthreads();
    #pragma unroll
    for (int p = 0; p < NSLOT/1024; p++) {
        int i = tid + p*1024;
        int e = g_topidx[i];
        int pos = s_off[e] + atomicAdd(&s_cur[e], 1);
        g_slot_tok[pos] = i >> 2;
        g_slot_w[pos]   = g_topw[i];
    }
}

// ================= k4: dual-subtile fp16 mma GEMM + swiglu =================
__global__ __launch_bounds__(256, 2) void k4_mlp1(
    const int* __restrict__ blocks, const int* __restrict__ scales,
    const float* __restrict__ bias)
{
    int e  = blockIdx.y;
    int nt = blockIdx.z;                  // 2I/BN = 16
    int cnt = g_counts[e];
    int m0 = blockIdx.x * BM;
    if (m0 >= cnt) return;
    bool do2 = (m0 + 64 < cnt);
    int off = g_offsets[e];

    extern __shared__ char dsm[];
    char* sb = (char*)(((uintptr_t)dsm + 1023) & ~(uintptr_t)1023);
    uint32_t sb32 = smem_u32(sb);
    __shared__ int s_tok[BM];

    const int ROWS = 2*IDIM, GRPS = HDIM/32;
    int tid = threadIdx.x;
    int lane = tid & 31, wid = tid >> 5;
    int wm = wid >> 2, wn = wid & 3;

    for (int i = tid; i < BM; i += 256) {
        int m = m0 + i;
        s_tok[i] = (m < cnt) ? g_slot_tok[off + m] : 0;
    }
    __syncthreads();

    int ci[4], cn[4], cj[4];
    #pragma unroll
    for (int p = 0; p < 4; p++) {
        ci[p] = (tid >> 5)*128 + p*32 + lane;
        cn[p] = ci[p] >> 3; cj[p] = ci[p] & 7;
    }
    const int* wbase = blocks + ((size_t)e*ROWS + nt*BN)*(size_t)GRPS*16;
    const int* sbase = scales + ((size_t)e*ROWS + nt*BN)*(size_t)GRPS;

    uint4    rw[4];
    uint32_t scl[4];

    auto issueLdg = [&](int kt) {
        #pragma unroll
        for (int p = 0; p < 4; p++) {
            rw[p] = *(const uint4*)(wbase + (size_t)cn[p]*GRPS*16
                                    + (kt*2 + (cj[p]>>2))*16 + (cj[p]&3)*4);
            scl[p] = (uint32_t)__ldg(sbase + cn[p]*GRPS + kt*2 + (cj[p]>>2));
        }
    };

    auto issueCp = [&](int kt) {
        int s = kt & 1;
        int c = tid & 7, mr = tid >> 3;
        cp16(sb32 + AS_OFF(s) + swz(mr*128 + c*16),
             g_t + (size_t)s_tok[mr]*HDIM + kt*BK + c*8);
        cp16(sb32 + AS_OFF(s) + swz((mr+32)*128 + c*16),
             g_t + (size_t)s_tok[mr+32]*HDIM + kt*BK + c*8);
        if (do2) {
            cp16(sb32 + AS_OFF(s) + swz((mr+64)*128 + c*16),
                 g_t + (size_t)s_tok[mr+64]*HDIM + kt*BK + c*8);
            cp16(sb32 + AS_OFF(s) + swz((mr+96)*128 + c*16),
                 g_t + (size_t)s_tok[mr+96]*HDIM + kt*BK + c*8);
        }
        CP_COMMIT();
    };

    auto decode = [&](int kt) {
        int s = kt & 1;
        #pragma unroll
        for (int p = 0; p < 4; p++) {
            uint32_t sc2 = ((scl[p] - 112u) << 10) * 0x00010001u;
            uint4 o = dec8(rw[p], sc2);
            *(uint4*)(sb + BS_OFF(s) + swz(cn[p]*128 + cj[p]*16)) = o;
        }
    };

    float acc[2][2][4][4] = {};          // [subtile][h][g][4]

    issueCp(0);
    issueLdg(0);
    CP_WAIT0();
    decode(0);

    #pragma unroll 1
    for (int kt = 0; kt < NK; kt++) {
        int s = kt & 1;
        if (kt + 1 < NK) issueLdg(kt + 1);   // regs free; overlaps barrier wait
        __syncthreads();
        if (kt + 1 < NK) issueCp(kt + 1);
        uint32_t Ab = sb32 + AS_OFF(s), Bb = sb32 + BS_OFF(s);
        #pragma unroll
        for (int kk = 0; kk < 4; kk++) {
            uint32_t b[4][2];
            {
                int r = lane & 7, kb = (lane >> 3) & 1, nb = lane >> 4;
                #pragma unroll
                for (int g2 = 0; g2 < 2; g2++) {
                    uint32_t ad = Bb + swz((wn*32 + g2*16 + nb*8 + r)*128 + kk*32 + kb*16);
                    ldsm4(b[2*g2][0], b[2*g2][1], b[2*g2+1][0], b[2*g2+1][1], ad);
                }
            }
            int r = lane & 7, sel = (lane >> 3) & 1, ks = lane >> 4;
            uint32_t a[2][4];
            #pragma unroll
            for (int h = 0; h < 2; h++) {
                uint32_t ad = Ab + swz((wm*32 + h*16 + sel*8 + r)*128 + kk*32 + ks*16);
                ldsm4(a[h][0], a[h][1], a[h][2], a[h][3], ad);
            }
            #pragma unroll
            for (int h = 0; h < 2; h++)
                #pragma unroll
                for (int g = 0; g < 4; g++)
                    mma_fp16(acc[0][h][g], a[h], b[g]);
            if (do2) {
                #pragma unroll
                for (int h = 0; h < 2; h++) {
                    uint32_t ad = Ab + swz((64 + wm*32 + h*16 + sel*8 + r)*128 + kk*32 + ks*16);
                    ldsm4(a[h][0], a[h][1], a[h][2], a[h][3], ad);
                }
                #pragma unroll
                for (int h = 0; h < 2; h++)
                    #pragma unroll
                    for (int g = 0; g < 4; g++)
                        mma_fp16(acc[1][h][g], a[h], b[g]);
            }
        }
        if (kt + 1 < NK) { decode(kt + 1); CP_WAIT0(); }
    }

    // ---- epilogue: bias + swiglu -> g_a (fp16) ----
    #pragma unroll
    for (int t = 0; t < 2; t++) {
        #pragma unroll
        for (int h = 0; h < 2; h++) {
            #pragma unroll
            for (int half = 0; half < 2; half++) {
                int m = m0 + t*64 + wm*32 + h*16 + (lane >> 2) + half*8;
                if (m >= cnt) continue;
                int slot = off + m;
                #pragma unroll
                for (int g = 0; g < 4; g++) {
                    int gcol = nt*BN + wn*32 + g*8 + 2*(lane & 3);
                    float hg = acc[t][h][g][half*2+0] + bias[(size_t)e*ROWS + gcol];
                    float hl = acc[t][h][g][half*2+1] + bias[(size_t)e*ROWS + gcol + 1];
                    hg = fminf(hg, 7.f);
                    hl = fminf(fmaxf(hl, -7.f), 7.f);
                    float aa = hg * (1.f / (1.f + expf(-1.702f * hg))) * (hl + 1.f);
                    g_a[(size_t)slot*IDIM + (gcol >> 1)] = __float2half_rn(aa);
                }
            }
        }
    }
}

// ================= k5: split-K dual-subtile fp16 mma GEMM + weighted scatter =================
__global__ __launch_bounds__(256, 2) void k5_mlp2(
    const int* __restrict__ blocks, const int* __restrict__ scales,
    const float* __restrict__ bias, float* __restrict__ out)
{
    int e  = blockIdx.y;
    int zz = blockIdx.z;                  // (HDIM/BN)*KSPLIT = 16
    int nt = zz & 7;
    int ksp = zz >> 3;                    // 0..1 k-split half
    int cnt = g_counts[e];
    int m0 = blockIdx.x * BM;
    if (m0 >= cnt) return;
    bool do2 = (m0 + 64 < cnt);
    int off = g_offsets[e];
    int kt0 = ksp * NKH;

    extern __shared__ char dsm[];
    char* sb = (char*)(((uintptr_t)dsm + 1023) & ~(uintptr_t)1023);
    uint32_t sb32 = smem_u32(sb);
    __shared__ int   s_tok[BM];
    __shared__ float s_w[BM];

    const int ROWS = HDIM, GRPS = IDIM/32;
    int tid = threadIdx.x;
    int lane = tid & 31, wid = tid >> 5;
    int wm = wid >> 2, wn = wid & 3;

    for (int i = tid; i < BM; i += 256) {
        int m = m0 + i;
        s_tok[i] = (m < cnt) ? g_slot_tok[off + m] : 0;
        s_w[i]   = (m < cnt) ? g_slot_w[off + m] : 0.f;
    }
    __syncthreads();

    int ci[4], cn[4], cj[4];
    #pragma unroll
    for (int p = 0; p < 4; p++) {
        ci[p] = (tid >> 5)*128 + p*32 + lane;
        cn[p] = ci[p] >> 3; cj[p] = ci[p] & 7;
    }
    const int* wbase = blocks + ((size_t)e*ROWS + nt*BN)*(size_t)GRPS*16;
    const int* sbase = scales + ((size_t)e*ROWS + nt*BN)*(size_t)GRPS;

    uint4    rw[4];
    uint32_t scl[4];

    auto issueLdg = [&](int kt) {
        #pragma unroll
        for (int p = 0; p < 4; p++) {
            rw[p] = *(const uint4*)(wbase + (size_t)cn[p]*GRPS*16
                                    + (kt*2 + (cj[p]>>2))*16 + (cj[p]&3)*4);
            scl[p] = (uint32_t)__ldg(sbase + cn[p]*GRPS + kt*2 + (cj[p]>>2));
        }
    };

    auto issueCp = [&](int kt) {
        int s = kt & 1;
        int c = tid & 7, mr = tid >> 3;
        int r0 = off + m0 + mr;       if (r0 > NSLOT-1) r0 = NSLOT-1;
        int r1 = off + m0 + mr + 32;  if (r1 > NSLOT-1) r1 = NSLOT-1;
        cp16(sb32 + AS_OFF(s) + swz(mr*128 + c*16), g_a + (size_t)r0*IDIM + kt*BK + c*8);
        cp16(sb32 + AS_OFF(s) + swz((mr+32)*128 + c*16), g_a + (size_t)r1*IDIM + kt*BK + c*8);
        if (do2) {
            int r2 = off + m0 + mr + 64;  if (r2 > NSLOT-1) r2 = NSLOT-1;
            int r3 = off + m0 + mr + 96;  if (r3 > NSLOT-1) r3 = NSLOT-1;
            cp16(sb32 + AS_OFF(s) + swz((mr+64)*128 + c*16), g_a + (size_t)r2*IDIM + kt*BK + c*8);
            cp16(sb32 + AS_OFF(s) + swz((mr+96)*128 + c*16), g_a + (size_t)r3*IDIM + kt*BK + c*8);
        }
        CP_COMMIT();
    };

    auto decode = [&](int kt) {
        int s = kt & 1;
        #pragma unroll
        for (int p = 0; p < 4; p++) {
            uint32_t sc2 = ((scl[p] - 112u) << 10) * 0x00010001u;
            uint4 o = dec8(rw[p], sc2);
            *(uint4*)(sb + BS_OFF(s) + swz(cn[p]*128 + cj[p]*16)) = o;
        }
    };

    float acc[2][2][4][4] = {};

    issueCp(kt0);
    issueLdg(kt0);
    CP_WAIT0();
    decode(kt0);

    #pragma unroll 1
    for (int ktl = 0; ktl < NKH; ktl++) {
        int kt = kt0 + ktl;
        int s = kt & 1;
        if (ktl + 1 < NKH) issueLdg(kt + 1);
        __syncthreads();
        if (ktl + 1 < NKH) issueCp(kt + 1);
        uint32_t Ab = sb32 + AS_OFF(s), Bb = sb32 + BS_OFF(s);
        #pragma unroll
        for (int kk = 0; kk < 4; kk++) {
            uint32_t b[4][2];
            {
                int r = lane & 7, kb = (lane >> 3) & 1, nb = lane >> 4;
                #pragma unroll
                for (int g2 = 0; g2 < 2; g2++) {
                    uint32_t ad = Bb + swz((wn*32 + g2*16 + nb*8 + r)*128 + kk*32 + kb*16);
                    ldsm4(b[2*g2][0], b[2*g2][1], b[2*g2+1][0], b[2*g2+1][1], ad);
                }
            }
            int r = lane & 7, sel = (lane >> 3) & 1, ks = lane >> 4;
            uint32_t a[2][4];
            #pragma unroll
            for (int h = 0; h < 2; h++) {
                uint32_t ad = Ab + swz((wm*32 + h*16 + sel*8 + r)*128 + kk*32 + ks*16);
                ldsm4(a[h][0], a[h][1], a[h][2], a[h][3], ad);
            }
            #pragma unroll
            for (int h = 0; h < 2; h++)
                #pragma unroll
                for (int g = 0; g < 4; g++)
                    mma_fp16(acc[0][h][g], a[h], b[g]);
            if (do2) {
                #pragma unroll
                for (int h = 0; h < 2; h++) {
                    uint32_t ad = Ab + swz((64 + wm*32 + h*16 + sel*8 + r)*128 + kk*32 + ks*16);
                    ldsm4(a[h][0], a[h][1], a[h][2], a[h][3], ad);
                }
                #pragma unroll
                for (int h = 0; h < 2; h++)
                    #pragma unroll
                    for (int g = 0; g < 4; g++)
                        mma_fp16(acc[1][h][g], a[h], b[g]);
            }
        }
        if (ktl + 1 < NKH) { decode(kt + 1); CP_WAIT0(); }
    }

    #pragma unroll
    for (int t = 0; t < 2; t++) {
        #pragma unroll
        for (int h = 0; h < 2; h++) {
            #pragma unroll
            for (int half = 0; half < 2; half++) {
                int mi = t*64 + wm*32 + h*16 + (lane >> 2) + half*8;
                if (m0 + mi >= cnt) continue;
                int tok = s_tok[mi];
                float rwt = s_w[mi];
                #pragma unroll
                for (int g = 0; g < 4; g++) {
                    int gcol = nt*BN + wn*32 + g*8 + 2*(lane & 3);
                    float b0 = (ksp == 0) ? bias[(size_t)e*HDIM + gcol]     : 0.f;
                    float b1 = (ksp == 0) ? bias[(size_t)e*HDIM + gcol + 1] : 0.f;
                    atomicAdd(&out[(size_t)tok*HDIM + gcol],     rwt * (acc[t][h][g][half*2+0] + b0));
                    atomicAdd(&out[(size_t)tok*HDIM + gcol + 1], rwt * (acc[t][h][g][half*2+1] + b1));
                }
            }
        }
    }
}

// ---------------- launch ----------------
extern "C" void kernel_launch(void* const* d_in, const int* in_sizes, int n_in,
                              void* d_out, int out_size)
{
    const float* x          = (const float*)d_in[0];
    const float* norm_w     = (const float*)d_in[1];
    const float* gate_w     = (const float*)d_in[2];
    const float* gate_b     = (const float*)d_in[3];
    const float* mlp1_bias  = (const float*)d_in[4];
    const float* mlp2_bias  = (const float*)d_in[5];
    const int*   mlp1_blocks= (const int*)d_in[6];
    const int*   mlp1_scales= (const int*)d_in[7];
    const int*   mlp2_blocks= (const int*)d_in[8];
    const int*   mlp2_scales= (const int*)d_in[9];
    float* out = (float*)d_out;

    cudaFuncSetAttribute(k4_mlp1, cudaFuncAttributeMaxDynamicSharedMemorySize, DSMEM_BYTES);
    cudaFuncSetAttribute(k5_mlp2, cudaFuncAttributeMaxDynamicSharedMemorySize, DSMEM_BYTES);

    k0_zero<<<1, 32>>>();
    k1_norm_gate<<<N_TOK/T4, 256>>>(x, norm_w, gate_w, gate_b, out);
    k2_route<<<1, 1024>>>();
    dim3 g4(N_TOK/BM, NEXP, (2*IDIM)/BN);           // (8, 32, 16)
    k4_mlp1<<<g4, 256, DSMEM_BYTES>>>(mlp1_blocks, mlp1_scales, mlp1_bias);
    dim3 g5(N_TOK/BM, NEXP, (HDIM/BN)*KSPLIT);      // (8, 32, 16)
    k5_mlp2<<<g5, 256, DSMEM_BYTES>>>(mlp2_blocks, mlp2_scales, mlp2_bias, out);
}